// round 4
// baseline (speedup 1.0000x reference)
#include <cuda_runtime.h>
#include <cuda_bf16.h>
#include <cstdint>

// Problem dims (fixed)
#define FDIM 1024
#define CDIM 128
#define BDIM 2048

#define BM 32
#define BN 64
#define BK 64
#define NITER (FDIM / BK)       // 16 stages, full K per CTA

// ---------------- scratch (static device, no allocs) ----------------
__device__ __nv_bfloat16 g_bh[CDIM * FDIM];   // softmax(w) hi
__device__ __nv_bfloat16 g_bl[CDIM * FDIM];   // softmax(w) lo

// ---------------- helpers ----------------
__device__ __forceinline__ uint32_t smem_u32(const void* p) {
    uint32_t a;
    asm("{ .reg .u64 t; cvta.to.shared.u64 t, %1; cvt.u32.u64 %0, t; }" : "=r"(a) : "l"(p));
    return a;
}
// 128B-row swizzle: byte col ^ ((row&7)<<4)
__device__ __forceinline__ uint32_t swz(uint32_t row, uint32_t colByte) {
    return row * 128u + (colByte ^ ((row & 7u) << 4));
}
#define CP_ASYNC16(sm, g) asm volatile("cp.async.cg.shared.global [%0], [%1], 16;" :: "r"(sm), "l"(g) : "memory")
#define CP_COMMIT()       asm volatile("cp.async.commit_group;" ::: "memory")
#define CP_WAIT1()        asm volatile("cp.async.wait_group 1;" ::: "memory")
#define CP_WAIT0()        asm volatile("cp.async.wait_group 0;" ::: "memory")

#define LDMATRIX_X4(r0, r1, r2, r3, addr)                                     \
    asm volatile("ldmatrix.sync.aligned.m8n8.x4.shared.b16 {%0,%1,%2,%3}, [%4];" \
                 : "=r"(r0), "=r"(r1), "=r"(r2), "=r"(r3) : "r"(addr))

#define MMA_BF16(d, a, b)                                                     \
    asm volatile("mma.sync.aligned.m16n8k16.row.col.f32.bf16.bf16.f32 "       \
                 "{%0,%1,%2,%3}, {%4,%5,%6,%7}, {%8,%9}, {%0,%1,%2,%3};"      \
                 : "+f"((d)[0]), "+f"((d)[1]), "+f"((d)[2]), "+f"((d)[3])     \
                 : "r"((a)[0]), "r"((a)[1]), "r"((a)[2]), "r"((a)[3]),        \
                   "r"((b)[0]), "r"((b)[1]))

__device__ __forceinline__ void split_bf16(float v, __nv_bfloat16& h, __nv_bfloat16& l) {
    h = __float2bfloat16(v);
    l = __float2bfloat16(v - __bfloat162float(h));
}

// ---------------------------------------------------------------------------
// Kernel 1: softmax(weight) rows -> Bh/Bl  [C, F] K-major
// ---------------------------------------------------------------------------
__global__ void __launch_bounds__(256) prep_w_kernel(const float* __restrict__ w) {
    const int c = blockIdx.x;
    const float* row = w + c * FDIM;
    __shared__ float red[256];
    const int t = threadIdx.x;

    float m = -1e30f;
    for (int f = t; f < FDIM; f += 256) m = fmaxf(m, row[f]);
    red[t] = m;
    __syncthreads();
    for (int s = 128; s > 0; s >>= 1) { if (t < s) red[t] = fmaxf(red[t], red[t + s]); __syncthreads(); }
    m = red[0];
    __syncthreads();

    float sum = 0.0f;
    for (int f = t; f < FDIM; f += 256) sum += __expf(row[f] - m);
    red[t] = sum;
    __syncthreads();
    for (int s = 128; s > 0; s >>= 1) { if (t < s) red[t] += red[t + s]; __syncthreads(); }
    const float inv = 1.0f / red[0];

    for (int f = t; f < FDIM; f += 256) {
        float p = __expf(row[f] - m) * inv;
        __nv_bfloat16 h, l;
        split_bf16(p, h, l);
        g_bh[c * FDIM + f] = h;
        g_bl[c * FDIM + f] = l;
    }
}

// ---------------------------------------------------------------------------
// Kernel 2: fused exp -> split -> HMMA GEMM -> log.
// grid = 64 Mtiles x 2 Nsplits = 128 CTAs, 128 threads (4 warps).
// Each CTA computes out[mtile*32 : +32, nsplit*64 : +64] over full K=1024.
// A: LDG x fp32 (prefetch 1 stage) -> exp+split in regs -> STS bf16 tiles.
// B: double-buffered cp.async of Bh/Bl.
// ---------------------------------------------------------------------------
// Per-stage smem block: As_h 4KB | As_l 4KB | Bs_h 8KB | Bs_l 8KB = 24KB
#define OFF_AH 0
#define OFF_AL 4096
#define OFF_BH 8192
#define OFF_BL 16384
#define STAGE_BYTES 24576
#define SMEM_TOTAL (2 * STAGE_BYTES)   // 49152

__device__ __forceinline__ void issue_b_loads(uint32_t stageBase, int nsplit, int kOff, int tid) {
    // Bh/Bl tiles: 64 rows x 128B = 512 16B-chunks each -> 4 per thread
#pragma unroll
    for (int t = 0; t < 4; t++) {
        const int idx = tid + t * 128;
        const uint32_t row = idx >> 3;       // 0..63
        const uint32_t c   = idx & 7;        // 16B chunk
        const size_t src = (size_t)(nsplit * BN + row) * FDIM + kOff + c * 8;
        CP_ASYNC16(stageBase + OFF_BH + swz(row, c * 16), g_bh + src);
        CP_ASYNC16(stageBase + OFF_BL + swz(row, c * 16), g_bl + src);
    }
    CP_COMMIT();
}

__global__ void __launch_bounds__(128) mma_kernel(const float* __restrict__ x,
                                                  float* __restrict__ out) {
    extern __shared__ char smem[];
    const uint32_t sbase = smem_u32(smem);
    const int tid  = threadIdx.x;
    const int warp = tid >> 5;     // n-range [warp*16, warp*16+16)
    const int lane = tid & 31;

    const int mtile  = (int)blockIdx.x >> 1;   // 0..63
    const int nsplit = (int)blockIdx.x & 1;    // 0..1

    float acc[2][2][4];
#pragma unroll
    for (int i = 0; i < 2; i++)
#pragma unroll
        for (int j = 0; j < 2; j++)
#pragma unroll
            for (int e = 0; e < 4; e++) acc[i][j][e] = 0.0f;

    // x LDG mapping: 32 rows x 16 float4/row = 512 float4 -> 4 per thread
    const uint32_t xrow = (uint32_t)tid >> 2;          // base rows: tid/4 -> use idx scheme below
    // (recomputed per element below)

    // ldmatrix lane address components
    const uint32_t aRow = (lane & 7) + ((lane >> 3) & 1) * 8;
    const uint32_t aCol = (lane >> 4) * 16;
    const uint32_t bRow = ((lane >> 4) & 1) * 8 + (lane & 7);
    const uint32_t bCol = ((lane >> 3) & 1) * 16;

    const float* xbase = x + (size_t)mtile * BM * FDIM;

    float4 xcur[4], xnext[4];
    // prologue: load x stage 0, issue B stage 0
#pragma unroll
    for (int t = 0; t < 4; t++) {
        const int idx = tid + t * 128;
        const uint32_t row = (uint32_t)idx >> 4;   // 0..31
        const uint32_t c4  = (uint32_t)idx & 15;   // float4 index in stage row
        xcur[t] = *reinterpret_cast<const float4*>(xbase + (size_t)row * FDIM + c4 * 4);
    }
    issue_b_loads(sbase, nsplit, 0, tid);

    for (int it = 0; it < NITER; it++) {
        const uint32_t cur = sbase + (uint32_t)(it & 1) * STAGE_BYTES;
        const bool has_next = (it + 1 < NITER);
        if (has_next) {
            issue_b_loads(sbase + (uint32_t)((it + 1) & 1) * STAGE_BYTES,
                          nsplit, (it + 1) * BK, tid);
#pragma unroll
            for (int t = 0; t < 4; t++) {
                const int idx = tid + t * 128;
                const uint32_t row = (uint32_t)idx >> 4;
                const uint32_t c4  = (uint32_t)idx & 15;
                xnext[t] = *reinterpret_cast<const float4*>(
                    xbase + (size_t)row * FDIM + (size_t)(it + 1) * BK + c4 * 4);
            }
        }

        // convert current x regs -> As tiles (bf16 hi/lo), 8B STS each
#pragma unroll
        for (int t = 0; t < 4; t++) {
            const int idx = tid + t * 128;
            const uint32_t row = (uint32_t)idx >> 4;
            const uint32_t c4  = (uint32_t)idx & 15;
            float4 v = xcur[t];
            float e0 = __expf(v.x), e1 = __expf(v.y), e2 = __expf(v.z), e3 = __expf(v.w);
            __nv_bfloat16 h0, l0, h1, l1, h2, l2, h3, l3;
            split_bf16(e0, h0, l0); split_bf16(e1, h1, l1);
            split_bf16(e2, h2, l2); split_bf16(e3, h3, l3);
            ushort4 hv = make_ushort4(__bfloat16_as_ushort(h0), __bfloat16_as_ushort(h1),
                                      __bfloat16_as_ushort(h2), __bfloat16_as_ushort(h3));
            ushort4 lv = make_ushort4(__bfloat16_as_ushort(l0), __bfloat16_as_ushort(l1),
                                      __bfloat16_as_ushort(l2), __bfloat16_as_ushort(l3));
            const uint32_t byteOff = swz(row, (c4 >> 1) * 16) + (c4 & 1) * 8;
            *reinterpret_cast<ushort4*>(smem + (cur - sbase) + OFF_AH + byteOff) = hv;
            *reinterpret_cast<ushort4*>(smem + (cur - sbase) + OFF_AL + byteOff) = lv;
        }

        if (has_next) { CP_WAIT1(); } else { CP_WAIT0(); }
        __syncthreads();

#pragma unroll
        for (int kstep = 0; kstep < BK / 16; kstep++) {
            const uint32_t kb = kstep * 32;
            uint32_t ah[2][4], al[2][4];
#pragma unroll
            for (int mi = 0; mi < 2; mi++) {
                const uint32_t row = mi * 16 + aRow;
                LDMATRIX_X4(ah[mi][0], ah[mi][1], ah[mi][2], ah[mi][3],
                            cur + OFF_AH + swz(row, kb + aCol));
                LDMATRIX_X4(al[mi][0], al[mi][1], al[mi][2], al[mi][3],
                            cur + OFF_AL + swz(row, kb + aCol));
            }
            uint32_t bh[2][2], bl[2][2];
            {
                const uint32_t row = warp * 16 + bRow;
                uint32_t r0, r1, r2, r3;
                LDMATRIX_X4(r0, r1, r2, r3, cur + OFF_BH + swz(row, kb + bCol));
                bh[0][0] = r0; bh[0][1] = r1; bh[1][0] = r2; bh[1][1] = r3;
                LDMATRIX_X4(r0, r1, r2, r3, cur + OFF_BL + swz(row, kb + bCol));
                bl[0][0] = r0; bl[0][1] = r1; bl[1][0] = r2; bl[1][1] = r3;
            }
#pragma unroll
            for (int ni = 0; ni < 2; ni++)
#pragma unroll
                for (int mi = 0; mi < 2; mi++) {
                    MMA_BF16(acc[mi][ni], ah[mi], bh[ni]);
                    MMA_BF16(acc[mi][ni], al[mi], bh[ni]);
                    MMA_BF16(acc[mi][ni], ah[mi], bl[ni]);
                }
        }
        __syncthreads();

#pragma unroll
        for (int t = 0; t < 4; t++) xcur[t] = xnext[t];
    }

    // Epilogue: log + direct store
#pragma unroll
    for (int mi = 0; mi < 2; mi++) {
#pragma unroll
        for (int ni = 0; ni < 2; ni++) {
            const int m = mtile * BM + mi * 16 + (lane >> 2);
            const int n = nsplit * BN + warp * 16 + ni * 8 + (lane & 3) * 2;
            *reinterpret_cast<float2*>(out + (size_t)m * CDIM + n) =
                make_float2(__logf(acc[mi][ni][0]), __logf(acc[mi][ni][1]));
            *reinterpret_cast<float2*>(out + (size_t)(m + 8) * CDIM + n) =
                make_float2(__logf(acc[mi][ni][2]), __logf(acc[mi][ni][3]));
        }
    }
}

// ---------------------------------------------------------------------------
extern "C" void kernel_launch(void* const* d_in, const int* in_sizes, int n_in,
                              void* d_out, int out_size) {
    const float* x = (const float*)d_in[0];
    const float* w = (const float*)d_in[1];
    if (n_in >= 2 && in_sizes[0] == CDIM * FDIM && in_sizes[1] == BDIM * FDIM) {
        w = (const float*)d_in[0];
        x = (const float*)d_in[1];
    }
    float* out = (float*)d_out;

    static bool attr_set = false;
    if (!attr_set) {
        cudaFuncSetAttribute(mma_kernel, cudaFuncAttributeMaxDynamicSharedMemorySize, SMEM_TOTAL);
        attr_set = true;
    }

    prep_w_kernel<<<CDIM, 256>>>(w);
    mma_kernel<<<(BDIM / BM) * (CDIM / BN), 128, SMEM_TOTAL>>>(x, out);
}